// round 16
// baseline (speedup 1.0000x reference)
#include <cuda_runtime.h>
#include <cuda_bf16.h>
#include <cstdint>

#define B_  16
#define L_  1024
#define U_  512
#define M_  (B_*L_)      // 16384

typedef __nv_bfloat16  bf16;
typedef __nv_bfloat162 bf162;

// ---------------------------------------------------------------------------
// Scratch (device globals; no allocation allowed)
// ---------------------------------------------------------------------------
__device__ float g_ps1[4*M_];           // s1 partials (per col-block)
__device__ float g_ps2[4*M_];           // s2 partials
__device__ float g_pr [8*M_];           // rowsum partials

__device__ bf16 g_ib  [M_*U_];          // inputs bf16
__device__ bf16 g_x0b [M_*U_];
__device__ bf16 g_x1b [M_*U_];
__device__ bf16 g_xw3 [M_*U_];          // x1 * w3
__device__ bf16 g_x1t [M_*U_];          // per-batch [U][L]
__device__ bf16 g_att [M_*U_];          // attention output
__device__ bf16 g_As  [(size_t)B_*L_*L_];  // exp(relu(scores))
__device__ bf16 g_tWt [2*U_*U_];
__device__ bf16 g_cWt [2*U_*U_];
__device__ bf16 g_ffWt[2*U_*U_];        // [512][1024]
__device__ bf16 g_frWt[2*U_*U_];        // [512][1024]

// ---------------------------------------------------------------------------
// PTX helpers (baseline PTX; compile at compute_103)
// ---------------------------------------------------------------------------
__device__ __forceinline__ uint32_t smem_u32(const void* p) {
    uint32_t a;
    asm("{ .reg .u64 t; cvta.to.shared.u64 t, %1; cvt.u32.u64 %0, t; }"
        : "=r"(a) : "l"(p));
    return a;
}
__device__ __forceinline__ void cpasync16(uint32_t dst, const void* src) {
    asm volatile("cp.async.cg.shared.global [%0], [%1], 16;"
                 :: "r"(dst), "l"(src));
}
#define CP_COMMIT() asm volatile("cp.async.commit_group;" ::: "memory")
#define CP_WAIT(n)  asm volatile("cp.async.wait_group %0;" :: "n"(n) : "memory")

#define LDSM4(r0, r1, r2, r3, addr) \
    asm volatile("ldmatrix.sync.aligned.m8n8.x4.shared.b16 {%0,%1,%2,%3}, [%4];" \
        : "=r"(r0), "=r"(r1), "=r"(r2), "=r"(r3) : "r"(addr))

__device__ __forceinline__ void mma_bf16(float* c, const uint32_t* a,
                                         uint32_t b0, uint32_t b1) {
    asm volatile(
        "mma.sync.aligned.m16n8k16.row.col.f32.bf16.bf16.f32 "
        "{%0,%1,%2,%3}, {%4,%5,%6,%7}, {%8,%9}, {%0,%1,%2,%3};"
        : "+f"(c[0]), "+f"(c[1]), "+f"(c[2]), "+f"(c[3])
        : "r"(a[0]), "r"(a[1]), "r"(a[2]), "r"(a[3]), "r"(b0), "r"(b1));
}

__device__ __forceinline__ float sigm(float v) {
    return 1.f / (1.f + __expf(-v));
}
__device__ __forceinline__ float2 b2f(bf162 p) {
    return make_float2(__bfloat162float(p.x), __bfloat162float(p.y));
}

#define KC 64
#define RB 128                 // row bytes (KC bf16)
#define BM 64                  // M tile rows (tail-friendly)
#define A_STAGE (BM*RB)        // 8 KB
#define B_STAGE (128*RB)       // 16 KB
#define NSTG 3
#define TPITCH 72              // bf16 pitch for transpose staging (64 rows + pad)
#define PSTAGE_OFF 20480       // byte offset of partial staging in dual smem

// ---------------------------------------------------------------------------
// DUAL bf16 GEMM (BM=64): two GEMMs sharing the A operand, fused epilogue.
// A split: chunks [0, csplit) from A, [csplit, nch) from A2 (both [M, U_]).
// mode 0 (highway): t=relu(acc1); c=sig(acc2); o = t*c + e*(1-c) -> Xbout bf16
//     extras: xw3o = o*w3[n]; x1to = per-batch transposed o;
//     ps1/ps2 = per-CTA partial row-dots of rounded o with w12 / w12+U.
// mode 1 (final):   z=sig(acc1);  r=sig(acc2); o = r*e2f + z*z -> Xout fp32
// Warp tile 32x32: m0=(wid>>2)*32, n0=(wid&3)*32, mt loop of 2.
// ---------------------------------------------------------------------------
__global__ __launch_bounds__(256, 1) void gemm_dual(
    const bf16* __restrict__ A, const bf16* __restrict__ A2, int csplit,
    const bf16* __restrict__ B1, const bf16* __restrict__ B2, long ldb,
    float* __restrict__ Xout, bf16* __restrict__ Xbout,
    const float* __restrict__ e2f, const bf16* __restrict__ e2b,
    int K,
    const float* __restrict__ b1, const float* __restrict__ b2,
    int mode,
    const float* __restrict__ w3, bf16* __restrict__ xw3o,
    bf16* __restrict__ x1to,
    const float* __restrict__ w12,
    float* __restrict__ ps1, float* __restrict__ ps2)
{
    extern __shared__ char smc[];
    const uint32_t as0  = smem_u32(smc);
    const uint32_t b1s0 = as0  + NSTG * A_STAGE;
    const uint32_t b2s0 = b1s0 + NSTG * B_STAGE;

    const int tid  = threadIdx.x;
    const int wid  = tid >> 5;
    const int lane = tid & 31;
    const int li   = lane & 7;
    const int q    = lane >> 3;
    const int ql   = q & 1;
    const int qh   = q >> 1;
    const int m0   = (wid >> 2) * 32;
    const int n0   = (wid & 3)  * 32;

    const int bm = blockIdx.y * BM;
    const int bn = blockIdx.x * 128;

    const int lrowA = tid >> 2;            // 0..63
    const int lcbA  = (tid & 3) * 2;       // chunk base, 2 chunks each
    const int lrowB = tid >> 1;            // 0..127
    const int lcbB  = (tid & 1) * 4;       // 4 chunks each
    const int nch   = K / KC;

    float acc1[2][4][4], acc2[2][4][4];
    #pragma unroll
    for (int i = 0; i < 2; i++)
        #pragma unroll
        for (int j = 0; j < 4; j++)
            #pragma unroll
            for (int k = 0; k < 4; k++) { acc1[i][j][k] = 0.f; acc2[i][j][k] = 0.f; }

    auto load_chunk = [&](int c) {
        const int st = c % NSTG;
        const bf16* ap = (c < csplit)
            ? A  + (long)(bm + lrowA) * U_ + c * KC
            : A2 + (long)(bm + lrowA) * U_ + (c - csplit) * KC;
        const bf16* b1p = B1 + (long)(bn + lrowB) * ldb + c * KC;
        const bf16* b2p = B2 + (long)(bn + lrowB) * ldb + c * KC;
        const uint32_t ad  = as0  + st * A_STAGE + lrowA * RB;
        const uint32_t bd1 = b1s0 + st * B_STAGE + lrowB * RB;
        const uint32_t bd2 = b2s0 + st * B_STAGE + lrowB * RB;
        const int swA = lrowA & 7, swB = lrowB & 7;
        #pragma unroll
        for (int j = 0; j < 2; j++) {
            const int ch = lcbA + j;
            cpasync16(ad + ((ch ^ swA) * 16), ap + ch * 8);
        }
        #pragma unroll
        for (int j = 0; j < 4; j++) {
            const int ch  = lcbB + j;
            const int cho = (ch ^ swB) * 16;
            cpasync16(bd1 + cho, b1p + ch * 8);
            cpasync16(bd2 + cho, b2p + ch * 8);
        }
        CP_COMMIT();
    };

    load_chunk(0);
    if (nch > 1) load_chunk(1);

    int rA[2], nB[2];
    #pragma unroll
    for (int mt = 0; mt < 2; mt++) rA[mt] = m0 + mt * 16 + li + ql * 8;
    #pragma unroll
    for (int p = 0; p < 2; p++)    nB[p] = n0 + p * 16 + qh * 8 + li;

    for (int c = 0; c < nch; c++) {
        const int st = c % NSTG;
        if (c + 1 < nch) CP_WAIT(1); else CP_WAIT(0);
        __syncthreads();
        if (c + 2 < nch) load_chunk(c + 2);

        const uint32_t asb  = as0  + st * A_STAGE;
        const uint32_t b1sb = b1s0 + st * B_STAGE;
        const uint32_t b2sb = b2s0 + st * B_STAGE;

        uint32_t afr[2][2][4], f1r[2][2][4], f2r[2][2][4];
        auto ld_frags = [&](int ks, int bu) {
            #pragma unroll
            for (int mt = 0; mt < 2; mt++) {
                const int r = rA[mt];
                const int ch = (ks * 2 + qh) ^ (r & 7);
                LDSM4(afr[bu][mt][0], afr[bu][mt][1], afr[bu][mt][2], afr[bu][mt][3],
                      asb + r * RB + ch * 16);
            }
            #pragma unroll
            for (int p = 0; p < 2; p++) {
                const int n = nB[p];
                const int ch = ((ks * 2 + ql) ^ (n & 7)) * 16;
                LDSM4(f1r[bu][p][0], f1r[bu][p][1], f1r[bu][p][2], f1r[bu][p][3],
                      b1sb + n * RB + ch);
                LDSM4(f2r[bu][p][0], f2r[bu][p][1], f2r[bu][p][2], f2r[bu][p][3],
                      b2sb + n * RB + ch);
            }
        };

        ld_frags(0, 0);
        #pragma unroll
        for (int ks = 0; ks < 4; ks++) {
            const int cur = ks & 1;
            if (ks < 3) ld_frags(ks + 1, cur ^ 1);
            #pragma unroll
            for (int nt = 0; nt < 4; nt++) {
                const int p = nt >> 1, h = (nt & 1) * 2;
                #pragma unroll
                for (int mt = 0; mt < 2; mt++) {
                    mma_bf16(acc1[mt][nt], afr[cur][mt],
                             f1r[cur][p][h], f1r[cur][p][h + 1]);
                    mma_bf16(acc2[mt][nt], afr[cur][mt],
                             f2r[cur][p][h], f2r[cur][p][h + 1]);
                }
            }
        }
    }

    // ---- fused epilogue ----
    const int grp = lane >> 2;
    const int tig = lane & 3;
    bf16*  stage = (bf16*)smc;                     // transpose staging [128][TPITCH]
    float* pst   = (float*)(smc + PSTAGE_OFF);     // partial staging [4][64][2]
    const int wcol = wid & 3;

    float2 w1v[4], w2v[4];
    if (mode == 0 && ps1) {
        #pragma unroll
        for (int nt = 0; nt < 4; nt++) {
            const int col = bn + n0 + nt * 8 + tig * 2;
            w1v[nt] = *(const float2*)(w12 + col);
            w2v[nt] = *(const float2*)(w12 + U_ + col);
        }
    }

    __syncthreads();   // mainloop smem reads done before staging reuse

    #pragma unroll
    for (int mt = 0; mt < 2; mt++) {
        const int rl  = m0 + mt * 16 + grp;     // local row 0..63
        const int row = bm + rl;
        float s1r = 0.f, s2r = 0.f, s1r8 = 0.f, s2r8 = 0.f;
        #pragma unroll
        for (int nt = 0; nt < 4; nt++) {
            const int cl  = n0 + nt * 8 + tig * 2;   // local col
            const int col = bn + cl;
            const float p10 = b1[col], p11 = b1[col + 1];
            const float p20 = b2[col], p21 = b2[col + 1];
            const long i0 = (long)row * U_ + col;
            const long i8 = (long)(row + 8) * U_ + col;
            float2 x0v, x8v;
            if (e2f) {
                x0v = *(const float2*)(e2f + i0);
                x8v = *(const float2*)(e2f + i8);
            } else {
                x0v = b2f(*(const bf162*)(e2b + i0));
                x8v = b2f(*(const bf162*)(e2b + i8));
            }
            float u0 = acc1[mt][nt][0] + p10, u1 = acc1[mt][nt][1] + p11;
            float u2 = acc1[mt][nt][2] + p10, u3 = acc1[mt][nt][3] + p11;
            float w0 = acc2[mt][nt][0] + p20, w1 = acc2[mt][nt][1] + p21;
            float w2 = acc2[mt][nt][2] + p20, w3v = acc2[mt][nt][3] + p21;
            if (mode == 0) {
                u0 = fmaxf(u0, 0.f); u1 = fmaxf(u1, 0.f);
                u2 = fmaxf(u2, 0.f); u3 = fmaxf(u3, 0.f);
                w0 = sigm(w0); w1 = sigm(w1); w2 = sigm(w2); w3v = sigm(w3v);
                const float o0 = u0 * w0 + x0v.x * (1.f - w0);
                const float o1 = u1 * w1 + x0v.y * (1.f - w1);
                const float o2 = u2 * w2 + x8v.x * (1.f - w2);
                const float o3 = u3 * w3v + x8v.y * (1.f - w3v);
                const bf162 pk0 = __floats2bfloat162_rn(o0, o1);
                const bf162 pk8 = __floats2bfloat162_rn(o2, o3);
                *(bf162*)(Xbout + i0) = pk0;
                *(bf162*)(Xbout + i8) = pk8;
                if (xw3o) {
                    const float2 wv = *(const float2*)(w3 + col);
                    *(bf162*)(xw3o + i0) = __floats2bfloat162_rn(o0 * wv.x, o1 * wv.y);
                    *(bf162*)(xw3o + i8) = __floats2bfloat162_rn(o2 * wv.x, o3 * wv.y);
                }
                if (x1to) {
                    stage[cl * TPITCH + rl]           = pk0.x;
                    stage[(cl + 1) * TPITCH + rl]     = pk0.y;
                    stage[cl * TPITCH + rl + 8]       = pk8.x;
                    stage[(cl + 1) * TPITCH + rl + 8] = pk8.y;
                }
                if (ps1) {
                    const float2 f0 = b2f(pk0), f8 = b2f(pk8);
                    s1r  += f0.x * w1v[nt].x + f0.y * w1v[nt].y;
                    s2r  += f0.x * w2v[nt].x + f0.y * w2v[nt].y;
                    s1r8 += f8.x * w1v[nt].x + f8.y * w1v[nt].y;
                    s2r8 += f8.x * w2v[nt].x + f8.y * w2v[nt].y;
                }
            } else {
                u0 = sigm(u0); u1 = sigm(u1); u2 = sigm(u2); u3 = sigm(u3);
                w0 = sigm(w0); w1 = sigm(w1); w2 = sigm(w2); w3v = sigm(w3v);
                const float o0 = w0 * x0v.x + u0 * u0;
                const float o1 = w1 * x0v.y + u1 * u1;
                const float o2 = w2 * x8v.x + u2 * u2;
                const float o3 = w3v * x8v.y + u3 * u3;
                *(float2*)(Xout + i0) = make_float2(o0, o1);
                *(float2*)(Xout + i8) = make_float2(o2, o3);
            }
        }
        if (mode == 0 && ps1) {
            #pragma unroll
            for (int msk = 1; msk <= 2; msk <<= 1) {
                s1r  += __shfl_xor_sync(0xffffffffu, s1r,  msk);
                s2r  += __shfl_xor_sync(0xffffffffu, s2r,  msk);
                s1r8 += __shfl_xor_sync(0xffffffffu, s1r8, msk);
                s2r8 += __shfl_xor_sync(0xffffffffu, s2r8, msk);
            }
            if (tig == 0) {
                pst[((wcol * 64 + rl)     << 1)]     = s1r;
                pst[((wcol * 64 + rl)     << 1) + 1] = s2r;
                pst[((wcol * 64 + rl + 8) << 1)]     = s1r8;
                pst[((wcol * 64 + rl + 8) << 1) + 1] = s2r8;
            }
        }
    }

    // ---- transposed write-out + partial reduce ----
    if (mode == 0 && (x1to || ps1)) {
        __syncthreads();
        if (x1to) {
            const int b0 = bm >> 10;         // batch (L_ = 1024)
            const int l0 = bm & 1023;
            const int cw = wid * 16;         // 16 cols per warp
            #pragma unroll
            for (int cc = 0; cc < 16; cc++) {
                const int c = cw + cc;
                const uint32_t v = *(const uint32_t*)(stage + c * TPITCH + lane * 2);
                *(uint32_t*)(x1to + ((long)b0 * U_ + bn + c) * L_ + l0 + lane * 2) = v;
            }
        }
        if (ps1 && tid < 128) {
            const int rl = tid >> 1, v = tid & 1;
            const float s = pst[((0 * 64 + rl) << 1) + v]
                          + pst[((1 * 64 + rl) << 1) + v]
                          + pst[((2 * 64 + rl) << 1) + v]
                          + pst[((3 * 64 + rl) << 1) + v];
            (v ? ps2 : ps1)[blockIdx.x * M_ + bm + rl] = s;
        }
    }
}

// ---------------------------------------------------------------------------
// Single bf16 GEMM (scores / att), BM=64, fragment double-buffered.
// ---------------------------------------------------------------------------
__global__ __launch_bounds__(256) void gemm_bf(
    const bf16* __restrict__ A,  long lda, long sA,
    const bf16* __restrict__ Bt, long ldb, long sB,
    bf16* __restrict__ Cb, long ldcb, long sCb,
    int K,
    const float* __restrict__ rowbias, long srb, int rbn,
    const float* __restrict__ colbias, long scb, int cbn,
    const float* __restrict__ addc,
    const float* __restrict__ rowscale, long srs, int rsn,
    int act,
    float* __restrict__ prow)
{
    extern __shared__ char smc[];
    const uint32_t as0 = smem_u32(smc);
    const uint32_t bs0 = as0 + NSTG * A_STAGE;

    const int tid  = threadIdx.x;
    const int wid  = tid >> 5;
    const int lane = tid & 31;
    const int li   = lane & 7;
    const int q    = lane >> 3;
    const int ql   = q & 1;
    const int qh   = q >> 1;
    const int m0   = (wid >> 2) * 32;
    const int n0   = (wid & 3)  * 32;

    const int bz = blockIdx.z;
    const int bm = blockIdx.y * BM;
    const int bn = blockIdx.x * 128;

    const bf16* Ag = A  + (long)bz * sA;
    const bf16* Bg = Bt + (long)bz * sB;

    const int lrowA = tid >> 2;
    const int lcbA  = (tid & 3) * 2;
    const int lrowB = tid >> 1;
    const int lcbB  = (tid & 1) * 4;
    const int nch   = K / KC;

    float acc[2][4][4];
    #pragma unroll
    for (int i = 0; i < 2; i++)
        #pragma unroll
        for (int j = 0; j < 4; j++)
            #pragma unroll
            for (int k = 0; k < 4; k++) acc[i][j][k] = 0.f;

    auto load_chunk = [&](int c) {
        const int st = c % NSTG;
        const bf16* ap = Ag + (long)(bm + lrowA) * lda + c * KC;
        const bf16* bp = Bg + (long)(bn + lrowB) * ldb + c * KC;
        const uint32_t ad = as0 + st * A_STAGE + lrowA * RB;
        const uint32_t bd = bs0 + st * B_STAGE + lrowB * RB;
        const int swA = lrowA & 7, swB = lrowB & 7;
        #pragma unroll
        for (int j = 0; j < 2; j++) {
            const int ch = lcbA + j;
            cpasync16(ad + ((ch ^ swA) * 16), ap + ch * 8);
        }
        #pragma unroll
        for (int j = 0; j < 4; j++) {
            const int ch = lcbB + j;
            cpasync16(bd + ((ch ^ swB) * 16), bp + ch * 8);
        }
        CP_COMMIT();
    };

    load_chunk(0);
    if (nch > 1) load_chunk(1);

    int rA[2], nB[2];
    #pragma unroll
    for (int mt = 0; mt < 2; mt++) rA[mt] = m0 + mt * 16 + li + ql * 8;
    #pragma unroll
    for (int p = 0; p < 2; p++)    nB[p] = n0 + p * 16 + qh * 8 + li;

    for (int c = 0; c < nch; c++) {
        const int st = c % NSTG;
        if (c + 1 < nch) CP_WAIT(1); else CP_WAIT(0);
        __syncthreads();
        if (c + 2 < nch) load_chunk(c + 2);

        const uint32_t asb = as0 + st * A_STAGE;
        const uint32_t bsb = bs0 + st * B_STAGE;

        uint32_t afr[2][2][4], bfr[2][2][4];
        auto ld_frags = [&](int ks, int bu) {
            #pragma unroll
            for (int mt = 0; mt < 2; mt++) {
                const int r = rA[mt];
                const int ch = (ks * 2 + qh) ^ (r & 7);
                LDSM4(afr[bu][mt][0], afr[bu][mt][1], afr[bu][mt][2], afr[bu][mt][3],
                      asb + r * RB + ch * 16);
            }
            #pragma unroll
            for (int p = 0; p < 2; p++) {
                const int n = nB[p];
                const int ch = (ks * 2 + ql) ^ (n & 7);
                LDSM4(bfr[bu][p][0], bfr[bu][p][1], bfr[bu][p][2], bfr[bu][p][3],
                      bsb + n * RB + ch * 16);
            }
        };

        ld_frags(0, 0);
        #pragma unroll
        for (int ks = 0; ks < 4; ks++) {
            const int cur = ks & 1;
            if (ks < 3) ld_frags(ks + 1, cur ^ 1);
            #pragma unroll
            for (int nt = 0; nt < 4; nt++) {
                const uint32_t b0 = bfr[cur][nt >> 1][(nt & 1) * 2];
                const uint32_t b1 = bfr[cur][nt >> 1][(nt & 1) * 2 + 1];
                #pragma unroll
                for (int mt = 0; mt < 2; mt++)
                    mma_bf16(acc[mt][nt], afr[cur][mt], b0, b1);
            }
        }
    }

    const int grp = lane >> 2;
    const int tig = lane & 3;
    const int wcol = wid & 3;
    bf16* Cbp = Cb + (long)bz * sCb;
    float* pst = (float*)smc;                // [4][64] partial staging
    const float a0 = addc ? addc[0] : 0.f;

    // colbias precompute (independent of mt); inline partial-sum if cbn>1
    float cbv[4][2];
    #pragma unroll
    for (int nt = 0; nt < 4; nt++) {
        cbv[nt][0] = 0.f; cbv[nt][1] = 0.f;
        if (colbias) {
            const int col = bn + n0 + nt * 8 + tig * 2;
            const long base = (long)bz * scb + col;
            #pragma unroll
            for (int j = 0; j < 8; j++) {
                if (j < cbn) {
                    cbv[nt][0] += colbias[(long)j * M_ + base];
                    cbv[nt][1] += colbias[(long)j * M_ + base + 1];
                }
            }
        }
    }

    __syncthreads();   // mainloop smem reads done before pst reuse

    #pragma unroll
    for (int mt = 0; mt < 2; mt++) {
        const int rl  = m0 + mt * 16 + grp;
        const int row = bm + rl;
        float rb0 = a0, rb8 = a0;
        if (rowbias) {
            const long base = (long)bz * srb + row;
            #pragma unroll
            for (int j = 0; j < 8; j++) {
                if (j < rbn) {
                    rb0 += rowbias[(long)j * M_ + base];
                    rb8 += rowbias[(long)j * M_ + base + 8];
                }
            }
        }
        float sc0 = 1.f, sc8 = 1.f;
        if (rowscale) {
            const long base = (long)bz * srs + row;
            float t0 = 0.f, t8 = 0.f;
            #pragma unroll
            for (int j = 0; j < 8; j++) {
                if (j < rsn) {
                    t0 += rowscale[(long)j * M_ + base];
                    t8 += rowscale[(long)j * M_ + base + 8];
                }
            }
            sc0 = 1.f / t0;
            sc8 = 1.f / t8;
        }
        float sr = 0.f, sr8 = 0.f;
        #pragma unroll
        for (int nt = 0; nt < 4; nt++) {
            const int col = bn + n0 + nt * 8 + tig * 2;
            float v0 = acc[mt][nt][0] + rb0 + cbv[nt][0];
            float v1 = acc[mt][nt][1] + rb0 + cbv[nt][1];
            float v2 = acc[mt][nt][2] + rb8 + cbv[nt][0];
            float v3 = acc[mt][nt][3] + rb8 + cbv[nt][1];
            if (act == 3) {
                v0 = __expf(fmaxf(v0, 0.f)); v1 = __expf(fmaxf(v1, 0.f));
                v2 = __expf(fmaxf(v2, 0.f)); v3 = __expf(fmaxf(v3, 0.f));
            } else {
                v0 *= sc0; v1 *= sc0; v2 *= sc8; v3 *= sc8;
            }
            const bf162 pk0 = __floats2bfloat162_rn(v0, v1);
            const bf162 pk8 = __floats2bfloat162_rn(v2, v3);
            *(bf162*)(Cbp + (long)row * ldcb + col)       = pk0;
            *(bf162*)(Cbp + (long)(row + 8) * ldcb + col) = pk8;
            if (act == 3 && prow) {
                const float2 f0 = b2f(pk0), f8 = b2f(pk8);
                sr  += f0.x + f0.y;
                sr8 += f8.x + f8.y;
            }
        }
        if (act == 3 && prow) {
            #pragma unroll
            for (int msk = 1; msk <= 2; msk <<= 1) {
                sr  += __shfl_xor_sync(0xffffffffu, sr,  msk);
                sr8 += __shfl_xor_sync(0xffffffffu, sr8, msk);
            }
            if (tig == 0) {
                pst[wcol * 64 + rl]     = sr;
                pst[wcol * 64 + rl + 8] = sr8;
            }
        }
    }

    if (act == 3 && prow) {
        __syncthreads();
        if (tid < 64) {
            const float s = pst[tid] + pst[64 + tid]
                          + pst[128 + tid] + pst[192 + tid];
            prow[(long)blockIdx.x * M_ + (long)bz * L_ + bm + tid] = s;
        }
    }
}

// ---------------------------------------------------------------------------
// Merged prologue: conv_inputs (blocks 0..8191) + 4 weight transposes
// ---------------------------------------------------------------------------
__global__ __launch_bounds__(256) void prologue(
    const float* __restrict__ in, bf16* __restrict__ ib,
    const float* __restrict__ tW, bf16* __restrict__ tWt,
    const float* __restrict__ cW, bf16* __restrict__ cWt,
    const float* __restrict__ ffW, bf16* __restrict__ ffWt,
    const float* __restrict__ frW, bf16* __restrict__ frWt)
{
    const int bid = blockIdx.x;
    if (bid < 8192) {
        const int i = bid * 256 + threadIdx.x;     // over M*U/4
        const float4 v = ((const float4*)in)[i];
        *(bf162*)(ib + (long)i * 4)     = __floats2bfloat162_rn(v.x, v.y);
        *(bf162*)(ib + (long)i * 4 + 2) = __floats2bfloat162_rn(v.z, v.w);
        return;
    }
    __shared__ float tile[32][33];
    const int s = bid - 8192;
    const int job = s >> 9;
    const int r   = s & 511;
    const float* src; bf16* dst; int R, Cc, r0, c0;
    if (job < 2) {
        const int layer = r >> 8, w = r & 255;
        src = (job == 0 ? tW : cW) + (long)layer * U_ * U_;
        dst = (job == 0 ? tWt : cWt) + (long)layer * U_ * U_;
        R = U_; Cc = U_; c0 = (w & 15) * 32; r0 = (w >> 4) * 32;
    } else {
        src = (job == 2 ? ffW : frW);
        dst = (job == 2 ? ffWt : frWt);
        R = 2 * U_; Cc = U_; c0 = (r & 15) * 32; r0 = (r >> 4) * 32;
    }
    const int tx = threadIdx.x & 31, ty = threadIdx.x >> 5;
    #pragma unroll
    for (int i2 = 0; i2 < 32; i2 += 8)
        tile[ty + i2][tx] = src[(long)(r0 + ty + i2) * Cc + c0 + tx];
    __syncthreads();
    #pragma unroll
    for (int i2 = 0; i2 < 32; i2 += 8)
        dst[(long)(c0 + ty + i2) * R + r0 + tx] = __float2bfloat16(tile[tx][ty + i2]);
}

// ---------------------------------------------------------------------------
// Launch
// ---------------------------------------------------------------------------
#define GEMM_SMEM (NSTG * (A_STAGE + B_STAGE))          // 72 KB (single)
#define DUAL_SMEM (NSTG * (A_STAGE + 2 * B_STAGE))      // 120 KB (dual)

extern "C" void kernel_launch(void* const* d_in, const int* in_sizes, int n_in,
                              void* d_out, int out_size)
{
    (void)in_sizes; (void)n_in; (void)out_size;
    const float* inputs = (const float*)d_in[0];
    const float* tW     = (const float*)d_in[1];
    const float* tb     = (const float*)d_in[2];
    const float* cW     = (const float*)d_in[3];
    const float* cb     = (const float*)d_in[4];
    const float* aW     = (const float*)d_in[5];
    const float* ab     = (const float*)d_in[6];
    const float* frW    = (const float*)d_in[7];
    const float* frb    = (const float*)d_in[8];
    const float* ffW    = (const float*)d_in[9];
    const float* ffb    = (const float*)d_in[10];
    float* out = (float*)d_out;

    float *ps1, *ps2, *pr;
    bf16 *ib, *x0b, *x1b, *xw3, *x1t, *att, *As, *tWt, *cWt, *ffWt, *frWt;
    cudaGetSymbolAddress((void**)&ps1,  g_ps1);
    cudaGetSymbolAddress((void**)&ps2,  g_ps2);
    cudaGetSymbolAddress((void**)&pr,   g_pr);
    cudaGetSymbolAddress((void**)&ib,   g_ib);
    cudaGetSymbolAddress((void**)&x0b,  g_x0b);
    cudaGetSymbolAddress((void**)&x1b,  g_x1b);
    cudaGetSymbolAddress((void**)&xw3,  g_xw3);
    cudaGetSymbolAddress((void**)&x1t,  g_x1t);
    cudaGetSymbolAddress((void**)&att,  g_att);
    cudaGetSymbolAddress((void**)&As,   g_As);
    cudaGetSymbolAddress((void**)&tWt,  g_tWt);
    cudaGetSymbolAddress((void**)&cWt,  g_cWt);
    cudaGetSymbolAddress((void**)&ffWt, g_ffWt);
    cudaGetSymbolAddress((void**)&frWt, g_frWt);

    cudaFuncSetAttribute(gemm_bf, cudaFuncAttributeMaxDynamicSharedMemorySize,
                         GEMM_SMEM);
    cudaFuncSetAttribute(gemm_dual, cudaFuncAttributeMaxDynamicSharedMemorySize,
                         DUAL_SMEM);

    // 1. merged prologue (inputs->bf16, 4 weight transposes)
    prologue<<<10240, 256>>>(inputs, ib, tW, tWt, cW, cWt,
                             ffW, ffWt, frW, frWt);

    dim3 gHW(U_/128, M_/BM);       // (4, 256) = 1024 CTAs
    // 2. highway layer 0 (dual)
    gemm_dual<<<gHW, 256, DUAL_SMEM>>>(ib, nullptr, 64, tWt, cWt, U_,
                                       nullptr, x0b, inputs, nullptr, U_,
                                       tb, cb, 0, nullptr, nullptr, nullptr,
                                       nullptr, nullptr, nullptr);
    // 3. highway layer 1 (dual) + fused xw3, x1^T, s1/s2 partials
    gemm_dual<<<gHW, 256, DUAL_SMEM>>>(x0b, nullptr, 64, tWt + U_*U_, cWt + U_*U_, U_,
                                       nullptr, x1b, nullptr, x0b, U_,
                                       tb + U_, cb + U_, 0,
                                       aW + 2*U_, xw3, x1t,
                                       aW, ps1, ps2);

    // 4. scores: As[b] = exp(relu( xw3 @ x1^T + Σps1 + Σps2 + ab )) + rowsum partials
    dim3 gS(L_/128, L_/BM, B_);    // (8, 16, 16) = 2048 CTAs
    gemm_bf<<<gS, 256, GEMM_SMEM>>>(xw3, U_, (long)L_*U_, x1b, U_, (long)L_*U_,
                                    As, L_, (long)L_*L_, U_,
                                    ps1, L_, 4, ps2, L_, 4, ab,
                                    nullptr, 0, 0, 3, pr);

    // 5. att = (expA @ x1) * (1/Σpr)[row] -> bf16 att [M,512]
    dim3 gAtt(U_/128, L_/BM, B_);  // (4, 16, 16) = 1024 CTAs
    gemm_bf<<<gAtt, 256, GEMM_SMEM>>>(As, L_, (long)L_*L_, x1t, L_, (long)U_*L_,
                                      att, U_, (long)L_*U_, L_,
                                      nullptr, 0, 0, nullptr, 0, 0, nullptr,
                                      pr, L_, 8, 0, nullptr);

    // 6. final dual over implicit concat [ib | att]:
    //    out = sig(.@frW+frb)*inputs + sig(.@ffW+ffb)^2
    gemm_dual<<<gHW, 256, DUAL_SMEM>>>(ib, att, 8, ffWt, frWt, 2*U_,
                                       out, nullptr, inputs, nullptr, 2*U_,
                                       ffb, frb, 1, nullptr, nullptr, nullptr,
                                       nullptr, nullptr, nullptr);
}

// round 17
// speedup vs baseline: 1.0364x; 1.0364x over previous
#include <cuda_runtime.h>
#include <cuda_bf16.h>
#include <cstdint>

#define B_  16
#define L_  1024
#define U_  512
#define M_  (B_*L_)      // 16384

typedef __nv_bfloat16  bf16;
typedef __nv_bfloat162 bf162;

// ---------------------------------------------------------------------------
// Scratch (device globals; no allocation allowed)
// ---------------------------------------------------------------------------
__device__ float g_ps1[4*M_];           // s1 partials (per col-block)
__device__ float g_ps2[4*M_];           // s2 partials
__device__ float g_pr [8*M_];           // rowsum partials

__device__ bf16 g_ib  [M_*U_];          // inputs bf16
__device__ bf16 g_x0b [M_*U_];
__device__ bf16 g_x1b [M_*U_];
__device__ bf16 g_xw3 [M_*U_];          // x1 * w3
__device__ bf16 g_x1t [M_*U_];          // per-batch [U][L]
__device__ bf16 g_att [M_*U_];          // attention output
__device__ bf16 g_As  [(size_t)B_*L_*L_];  // exp(relu(scores))
__device__ bf16 g_tWt [2*U_*U_];
__device__ bf16 g_cWt [2*U_*U_];
__device__ bf16 g_ffWt[2*U_*U_];        // [512][1024]
__device__ bf16 g_frWt[2*U_*U_];        // [512][1024]

// ---------------------------------------------------------------------------
// PTX helpers (baseline PTX; compile at compute_103)
// ---------------------------------------------------------------------------
__device__ __forceinline__ uint32_t smem_u32(const void* p) {
    uint32_t a;
    asm("{ .reg .u64 t; cvta.to.shared.u64 t, %1; cvt.u32.u64 %0, t; }"
        : "=r"(a) : "l"(p));
    return a;
}
__device__ __forceinline__ void cpasync16(uint32_t dst, const void* src) {
    asm volatile("cp.async.cg.shared.global [%0], [%1], 16;"
                 :: "r"(dst), "l"(src));
}
#define CP_COMMIT() asm volatile("cp.async.commit_group;" ::: "memory")
#define CP_WAIT(n)  asm volatile("cp.async.wait_group %0;" :: "n"(n) : "memory")

#define LDSM4(r0, r1, r2, r3, addr) \
    asm volatile("ldmatrix.sync.aligned.m8n8.x4.shared.b16 {%0,%1,%2,%3}, [%4];" \
        : "=r"(r0), "=r"(r1), "=r"(r2), "=r"(r3) : "r"(addr))

__device__ __forceinline__ void mma_bf16(float* c, const uint32_t* a,
                                         uint32_t b0, uint32_t b1) {
    asm volatile(
        "mma.sync.aligned.m16n8k16.row.col.f32.bf16.bf16.f32 "
        "{%0,%1,%2,%3}, {%4,%5,%6,%7}, {%8,%9}, {%0,%1,%2,%3};"
        : "+f"(c[0]), "+f"(c[1]), "+f"(c[2]), "+f"(c[3])
        : "r"(a[0]), "r"(a[1]), "r"(a[2]), "r"(a[3]), "r"(b0), "r"(b1));
}

__device__ __forceinline__ float sigm(float v) {
    return 1.f / (1.f + __expf(-v));
}
__device__ __forceinline__ float2 b2f(bf162 p) {
    return make_float2(__bfloat162float(p.x), __bfloat162float(p.y));
}

#define KC 64
#define RB 128                 // row bytes (KC bf16)
#define STAGE_B (128*RB)       // 16 KB
#define NSTG 3
#define TPITCH 136             // bf16 pitch for transpose staging
#define PSTAGE_OFF 36864       // byte offset of partial staging in dual smem

// ---------------------------------------------------------------------------
// DUAL bf16 GEMM: two GEMMs sharing the A operand, fused combine epilogue.
// A operand split: chunks [0, csplit) stream from A, [csplit, nch) from A2
// (both row-major [M, U_]) — implements the implicit concat without a buffer.
// mode 0 (highway): t=relu(acc1); c=sig(acc2); o = t*c + e*(1-c) -> Xbout bf16
//     extras: xw3o = o*w3[n]; x1to = per-batch transposed o;
//     ps1/ps2 = per-CTA partial row-dots of rounded o with w12 / w12+U.
// mode 1 (final):   z=sig(acc1);  r=sig(acc2); o = r*e2f + z*z -> Xout fp32
// ---------------------------------------------------------------------------
__global__ __launch_bounds__(256, 1) void gemm_dual(
    const bf16* __restrict__ A, const bf16* __restrict__ A2, int csplit,
    const bf16* __restrict__ B1, const bf16* __restrict__ B2, long ldb,
    float* __restrict__ Xout, bf16* __restrict__ Xbout,
    const float* __restrict__ e2f, const bf16* __restrict__ e2b,
    int K,
    const float* __restrict__ b1, const float* __restrict__ b2,
    int mode,
    const float* __restrict__ w3, bf16* __restrict__ xw3o,
    bf16* __restrict__ x1to,
    const float* __restrict__ w12,
    float* __restrict__ ps1, float* __restrict__ ps2)
{
    extern __shared__ char smc[];
    const uint32_t as0  = smem_u32(smc);
    const uint32_t b1s0 = as0  + NSTG * STAGE_B;
    const uint32_t b2s0 = b1s0 + NSTG * STAGE_B;

    const int tid  = threadIdx.x;
    const int wid  = tid >> 5;
    const int lane = tid & 31;
    const int li   = lane & 7;
    const int q    = lane >> 3;
    const int ql   = q & 1;
    const int qh   = q >> 1;
    const int m0   = (wid >> 2) * 64;
    const int n0   = (wid & 3)  * 32;

    const int bm = blockIdx.y * 128;
    const int bn = blockIdx.x * 128;

    const int lrow = tid >> 1;
    const int lcb  = (tid & 1) * 4;
    const int nch  = K / KC;

    float acc1[4][4][4], acc2[4][4][4];
    #pragma unroll
    for (int i = 0; i < 4; i++)
        #pragma unroll
        for (int j = 0; j < 4; j++)
            #pragma unroll
            for (int k = 0; k < 4; k++) { acc1[i][j][k] = 0.f; acc2[i][j][k] = 0.f; }

    auto load_chunk = [&](int c) {
        const int st = c % NSTG;
        const bf16* ap = (c < csplit)
            ? A  + (long)(bm + lrow) * U_ + c * KC
            : A2 + (long)(bm + lrow) * U_ + (c - csplit) * KC;
        const bf16* b1p = B1 + (long)(bn + lrow) * ldb + c * KC;
        const bf16* b2p = B2 + (long)(bn + lrow) * ldb + c * KC;
        const uint32_t ad  = as0  + st * STAGE_B + lrow * RB;
        const uint32_t bd1 = b1s0 + st * STAGE_B + lrow * RB;
        const uint32_t bd2 = b2s0 + st * STAGE_B + lrow * RB;
        const int sw = lrow & 7;
        #pragma unroll
        for (int j = 0; j < 4; j++) {
            const int ch  = lcb + j;
            const int cho = (ch ^ sw) * 16;
            cpasync16(ad  + cho, ap  + ch * 8);
            cpasync16(bd1 + cho, b1p + ch * 8);
            cpasync16(bd2 + cho, b2p + ch * 8);
        }
        CP_COMMIT();
    };

    load_chunk(0);
    if (nch > 1) load_chunk(1);

    int rA[4], nB[2];
    #pragma unroll
    for (int mt = 0; mt < 4; mt++) rA[mt] = m0 + mt * 16 + li + ql * 8;
    #pragma unroll
    for (int p = 0; p < 2; p++)    nB[p] = n0 + p * 16 + qh * 8 + li;

    for (int c = 0; c < nch; c++) {
        const int st = c % NSTG;
        if (c + 1 < nch) CP_WAIT(1); else CP_WAIT(0);
        __syncthreads();
        if (c + 2 < nch) load_chunk(c + 2);

        const uint32_t asb  = as0  + st * STAGE_B;
        const uint32_t b1sb = b1s0 + st * STAGE_B;
        const uint32_t b2sb = b2s0 + st * STAGE_B;

        uint32_t afr[2][4][4], f1r[2][2][4], f2r[2][2][4];
        auto ld_frags = [&](int ks, int bu) {
            #pragma unroll
            for (int mt = 0; mt < 4; mt++) {
                const int r = rA[mt];
                const int ch = (ks * 2 + qh) ^ (r & 7);
                LDSM4(afr[bu][mt][0], afr[bu][mt][1], afr[bu][mt][2], afr[bu][mt][3],
                      asb + r * RB + ch * 16);
            }
            #pragma unroll
            for (int p = 0; p < 2; p++) {
                const int n = nB[p];
                const int ch = ((ks * 2 + ql) ^ (n & 7)) * 16;
                LDSM4(f1r[bu][p][0], f1r[bu][p][1], f1r[bu][p][2], f1r[bu][p][3],
                      b1sb + n * RB + ch);
                LDSM4(f2r[bu][p][0], f2r[bu][p][1], f2r[bu][p][2], f2r[bu][p][3],
                      b2sb + n * RB + ch);
            }
        };

        ld_frags(0, 0);
        #pragma unroll
        for (int ks = 0; ks < 4; ks++) {
            const int cur = ks & 1;
            if (ks < 3) ld_frags(ks + 1, cur ^ 1);
            #pragma unroll
            for (int nt = 0; nt < 4; nt++) {
                const int p = nt >> 1, h = (nt & 1) * 2;
                #pragma unroll
                for (int mt = 0; mt < 4; mt++) {
                    mma_bf16(acc1[mt][nt], afr[cur][mt],
                             f1r[cur][p][h], f1r[cur][p][h + 1]);
                    mma_bf16(acc2[mt][nt], afr[cur][mt],
                             f2r[cur][p][h], f2r[cur][p][h + 1]);
                }
            }
        }
    }

    // ---- fused epilogue ----
    const int grp = lane >> 2;
    const int tig = lane & 3;
    bf16*  stage = (bf16*)smc;                     // transpose staging
    float* pst   = (float*)(smc + PSTAGE_OFF);     // partial staging [4][128][2]
    const int wcol = wid & 3;

    float2 w1v[4], w2v[4];
    if (mode == 0 && ps1) {
        #pragma unroll
        for (int nt = 0; nt < 4; nt++) {
            const int col = bn + n0 + nt * 8 + tig * 2;
            w1v[nt] = *(const float2*)(w12 + col);
            w2v[nt] = *(const float2*)(w12 + U_ + col);
        }
    }

    __syncthreads();   // mainloop smem reads done before staging reuse

    #pragma unroll
    for (int mt = 0; mt < 4; mt++) {
        const int rl  = m0 + mt * 16 + grp;     // local row
        const int row = bm + rl;
        float s1r = 0.f, s2r = 0.f, s1r8 = 0.f, s2r8 = 0.f;
        #pragma unroll
        for (int nt = 0; nt < 4; nt++) {
            const int cl  = n0 + nt * 8 + tig * 2;   // local col
            const int col = bn + cl;
            const float p10 = b1[col], p11 = b1[col + 1];
            const float p20 = b2[col], p21 = b2[col + 1];
            const long i0 = (long)row * U_ + col;
            const long i8 = (long)(row + 8) * U_ + col;
            float2 x0v, x8v;
            if (e2f) {
                x0v = *(const float2*)(e2f + i0);
                x8v = *(const float2*)(e2f + i8);
            } else {
                x0v = b2f(*(const bf162*)(e2b + i0));
                x8v = b2f(*(const bf162*)(e2b + i8));
            }
            float u0 = acc1[mt][nt][0] + p10, u1 = acc1[mt][nt][1] + p11;
            float u2 = acc1[mt][nt][2] + p10, u3 = acc1[mt][nt][3] + p11;
            float w0 = acc2[mt][nt][0] + p20, w1 = acc2[mt][nt][1] + p21;
            float w2 = acc2[mt][nt][2] + p20, w3v = acc2[mt][nt][3] + p21;
            if (mode == 0) {
                u0 = fmaxf(u0, 0.f); u1 = fmaxf(u1, 0.f);
                u2 = fmaxf(u2, 0.f); u3 = fmaxf(u3, 0.f);
                w0 = sigm(w0); w1 = sigm(w1); w2 = sigm(w2); w3v = sigm(w3v);
                const float o0 = u0 * w0 + x0v.x * (1.f - w0);
                const float o1 = u1 * w1 + x0v.y * (1.f - w1);
                const float o2 = u2 * w2 + x8v.x * (1.f - w2);
                const float o3 = u3 * w3v + x8v.y * (1.f - w3v);
                const bf162 pk0 = __floats2bfloat162_rn(o0, o1);
                const bf162 pk8 = __floats2bfloat162_rn(o2, o3);
                *(bf162*)(Xbout + i0) = pk0;
                *(bf162*)(Xbout + i8) = pk8;
                if (xw3o) {
                    const float2 wv = *(const float2*)(w3 + col);
                    *(bf162*)(xw3o + i0) = __floats2bfloat162_rn(o0 * wv.x, o1 * wv.y);
                    *(bf162*)(xw3o + i8) = __floats2bfloat162_rn(o2 * wv.x, o3 * wv.y);
                }
                if (x1to) {
                    stage[cl * TPITCH + rl]           = pk0.x;
                    stage[(cl + 1) * TPITCH + rl]     = pk0.y;
                    stage[cl * TPITCH + rl + 8]       = pk8.x;
                    stage[(cl + 1) * TPITCH + rl + 8] = pk8.y;
                }
                if (ps1) {
                    const float2 f0 = b2f(pk0), f8 = b2f(pk8);
                    s1r  += f0.x * w1v[nt].x + f0.y * w1v[nt].y;
                    s2r  += f0.x * w2v[nt].x + f0.y * w2v[nt].y;
                    s1r8 += f8.x * w1v[nt].x + f8.y * w1v[nt].y;
                    s2r8 += f8.x * w2v[nt].x + f8.y * w2v[nt].y;
                }
            } else {
                u0 = sigm(u0); u1 = sigm(u1); u2 = sigm(u2); u3 = sigm(u3);
                w0 = sigm(w0); w1 = sigm(w1); w2 = sigm(w2); w3v = sigm(w3v);
                const float o0 = w0 * x0v.x + u0 * u0;
                const float o1 = w1 * x0v.y + u1 * u1;
                const float o2 = w2 * x8v.x + u2 * u2;
                const float o3 = w3v * x8v.y + u3 * u3;
                *(float2*)(Xout + i0) = make_float2(o0, o1);
                *(float2*)(Xout + i8) = make_float2(o2, o3);
            }
        }
        if (mode == 0 && ps1) {
            #pragma unroll
            for (int msk = 1; msk <= 2; msk <<= 1) {
                s1r  += __shfl_xor_sync(0xffffffffu, s1r,  msk);
                s2r  += __shfl_xor_sync(0xffffffffu, s2r,  msk);
                s1r8 += __shfl_xor_sync(0xffffffffu, s1r8, msk);
                s2r8 += __shfl_xor_sync(0xffffffffu, s2r8, msk);
            }
            if (tig == 0) {
                pst[((wcol * 128 + rl)     << 1)]     = s1r;
                pst[((wcol * 128 + rl)     << 1) + 1] = s2r;
                pst[((wcol * 128 + rl + 8) << 1)]     = s1r8;
                pst[((wcol * 128 + rl + 8) << 1) + 1] = s2r8;
            }
        }
    }

    // ---- transposed write-out + partial reduce ----
    if (mode == 0 && (x1to || ps1)) {
        __syncthreads();
        if (x1to) {
            const int b0 = bm >> 10;         // batch (L_ = 1024)
            const int l0 = bm & 1023;
            const int cw = wid * 16;         // 16 cols per warp
            #pragma unroll
            for (int cc = 0; cc < 16; cc++) {
                const int c = cw + cc;
                const uint2 v = *(const uint2*)(stage + c * TPITCH + lane * 4);
                *(uint2*)(x1to + ((long)b0 * U_ + bn + c) * L_ + l0 + lane * 4) = v;
            }
        }
        if (ps1) {
            const int rl = tid >> 1, v = tid & 1;
            const float s = pst[((0 * 128 + rl) << 1) + v]
                          + pst[((1 * 128 + rl) << 1) + v]
                          + pst[((2 * 128 + rl) << 1) + v]
                          + pst[((3 * 128 + rl) << 1) + v];
            (v ? ps2 : ps1)[blockIdx.x * M_ + bm + rl] = s;
        }
    }
}

// ---------------------------------------------------------------------------
// Single bf16 GEMM (scores / att) with fragment double-buffering.
// ---------------------------------------------------------------------------
__global__ __launch_bounds__(256) void gemm_bf(
    const bf16* __restrict__ A,  long lda, long sA,
    const bf16* __restrict__ Bt, long ldb, long sB,
    bf16* __restrict__ Cb, long ldcb, long sCb,
    int K,
    const float* __restrict__ rowbias, long srb, int rbn,
    const float* __restrict__ colbias, long scb, int cbn,
    const float* __restrict__ addc,
    const float* __restrict__ rowscale, long srs, int rsn,
    int act,
    float* __restrict__ prow)
{
    extern __shared__ char smc[];
    const uint32_t as0 = smem_u32(smc);
    const uint32_t bs0 = as0 + NSTG * STAGE_B;

    const int tid  = threadIdx.x;
    const int wid  = tid >> 5;
    const int lane = tid & 31;
    const int li   = lane & 7;
    const int q    = lane >> 3;
    const int ql   = q & 1;
    const int qh   = q >> 1;
    const int m0   = (wid >> 2) * 64;
    const int n0   = (wid & 3)  * 32;

    const int bz = blockIdx.z;
    const int bm = blockIdx.y * 128;
    const int bn = blockIdx.x * 128;

    const bf16* Ag = A  + (long)bz * sA;
    const bf16* Bg = Bt + (long)bz * sB;

    const int lrow = tid >> 1;
    const int lcb  = (tid & 1) * 4;
    const int nch  = K / KC;

    float acc[4][4][4];
    #pragma unroll
    for (int i = 0; i < 4; i++)
        #pragma unroll
        for (int j = 0; j < 4; j++)
            #pragma unroll
            for (int k = 0; k < 4; k++) acc[i][j][k] = 0.f;

    auto load_chunk = [&](int c) {
        const int st = c % NSTG;
        const bf16* ap = Ag + (long)(bm + lrow) * lda + c * KC;
        const bf16* bp = Bg + (long)(bn + lrow) * ldb + c * KC;
        const uint32_t ad = as0 + st * STAGE_B + lrow * RB;
        const uint32_t bd = bs0 + st * STAGE_B + lrow * RB;
        const int sw = lrow & 7;
        #pragma unroll
        for (int j = 0; j < 4; j++) {
            const int ch = lcb + j;
            const int cho = (ch ^ sw) * 16;
            cpasync16(ad + cho, ap + ch * 8);
            cpasync16(bd + cho, bp + ch * 8);
        }
        CP_COMMIT();
    };

    load_chunk(0);
    if (nch > 1) load_chunk(1);

    int rA[4], nB[2];
    #pragma unroll
    for (int mt = 0; mt < 4; mt++) rA[mt] = m0 + mt * 16 + li + ql * 8;
    #pragma unroll
    for (int p = 0; p < 2; p++)    nB[p] = n0 + p * 16 + qh * 8 + li;

    for (int c = 0; c < nch; c++) {
        const int st = c % NSTG;
        if (c + 1 < nch) CP_WAIT(1); else CP_WAIT(0);
        __syncthreads();
        if (c + 2 < nch) load_chunk(c + 2);

        const uint32_t asb = as0 + st * STAGE_B;
        const uint32_t bsb = bs0 + st * STAGE_B;

        uint32_t afr[2][4][4], bfr[2][2][4];
        auto ld_frags = [&](int ks, int bu) {
            #pragma unroll
            for (int mt = 0; mt < 4; mt++) {
                const int r = rA[mt];
                const int ch = (ks * 2 + qh) ^ (r & 7);
                LDSM4(afr[bu][mt][0], afr[bu][mt][1], afr[bu][mt][2], afr[bu][mt][3],
                      asb + r * RB + ch * 16);
            }
            #pragma unroll
            for (int p = 0; p < 2; p++) {
                const int n = nB[p];
                const int ch = (ks * 2 + ql) ^ (n & 7);
                LDSM4(bfr[bu][p][0], bfr[bu][p][1], bfr[bu][p][2], bfr[bu][p][3],
                      bsb + n * RB + ch * 16);
            }
        };

        ld_frags(0, 0);
        #pragma unroll
        for (int ks = 0; ks < 4; ks++) {
            const int cur = ks & 1;
            if (ks < 3) ld_frags(ks + 1, cur ^ 1);
            #pragma unroll
            for (int nt = 0; nt < 4; nt++) {
                const uint32_t b0 = bfr[cur][nt >> 1][(nt & 1) * 2];
                const uint32_t b1 = bfr[cur][nt >> 1][(nt & 1) * 2 + 1];
                #pragma unroll
                for (int mt = 0; mt < 4; mt++)
                    mma_bf16(acc[mt][nt], afr[cur][mt], b0, b1);
            }
        }
    }

    const int grp = lane >> 2;
    const int tig = lane & 3;
    const int wcol = wid & 3;
    bf16* Cbp = Cb + (long)bz * sCb;
    float* pst = (float*)smc;                // [4][128] partial staging
    const float a0 = addc ? addc[0] : 0.f;

    // colbias precompute (independent of mt); inline partial-sum if cbn>1
    float cbv[4][2];
    #pragma unroll
    for (int nt = 0; nt < 4; nt++) {
        cbv[nt][0] = 0.f; cbv[nt][1] = 0.f;
        if (colbias) {
            const int col = bn + n0 + nt * 8 + tig * 2;
            const long base = (long)bz * scb + col;
            #pragma unroll
            for (int j = 0; j < 8; j++) {
                if (j < cbn) {
                    cbv[nt][0] += colbias[(long)j * M_ + base];
                    cbv[nt][1] += colbias[(long)j * M_ + base + 1];
                }
            }
        }
    }

    __syncthreads();   // mainloop smem reads done before pst reuse

    #pragma unroll
    for (int mt = 0; mt < 4; mt++) {
        const int rl  = m0 + mt * 16 + grp;
        const int row = bm + rl;
        float rb0 = a0, rb8 = a0;
        if (rowbias) {
            const long base = (long)bz * srb + row;
            #pragma unroll
            for (int j = 0; j < 8; j++) {
                if (j < rbn) {
                    rb0 += rowbias[(long)j * M_ + base];
                    rb8 += rowbias[(long)j * M_ + base + 8];
                }
            }
        }
        float sc0 = 1.f, sc8 = 1.f;
        if (rowscale) {
            const long base = (long)bz * srs + row;
            float t0 = 0.f, t8 = 0.f;
            #pragma unroll
            for (int j = 0; j < 8; j++) {
                if (j < rsn) {
                    t0 += rowscale[(long)j * M_ + base];
                    t8 += rowscale[(long)j * M_ + base + 8];
                }
            }
            sc0 = 1.f / t0;
            sc8 = 1.f / t8;
        }
        float sr = 0.f, sr8 = 0.f;
        #pragma unroll
        for (int nt = 0; nt < 4; nt++) {
            const int col = bn + n0 + nt * 8 + tig * 2;
            float v0 = acc[mt][nt][0] + rb0 + cbv[nt][0];
            float v1 = acc[mt][nt][1] + rb0 + cbv[nt][1];
            float v2 = acc[mt][nt][2] + rb8 + cbv[nt][0];
            float v3 = acc[mt][nt][3] + rb8 + cbv[nt][1];
            if (act == 3) {
                v0 = __expf(fmaxf(v0, 0.f)); v1 = __expf(fmaxf(v1, 0.f));
                v2 = __expf(fmaxf(v2, 0.f)); v3 = __expf(fmaxf(v3, 0.f));
            } else {
                v0 *= sc0; v1 *= sc0; v2 *= sc8; v3 *= sc8;
            }
            const bf162 pk0 = __floats2bfloat162_rn(v0, v1);
            const bf162 pk8 = __floats2bfloat162_rn(v2, v3);
            *(bf162*)(Cbp + (long)row * ldcb + col)       = pk0;
            *(bf162*)(Cbp + (long)(row + 8) * ldcb + col) = pk8;
            if (act == 3 && prow) {
                const float2 f0 = b2f(pk0), f8 = b2f(pk8);
                sr  += f0.x + f0.y;
                sr8 += f8.x + f8.y;
            }
        }
        if (act == 3 && prow) {
            #pragma unroll
            for (int msk = 1; msk <= 2; msk <<= 1) {
                sr  += __shfl_xor_sync(0xffffffffu, sr,  msk);
                sr8 += __shfl_xor_sync(0xffffffffu, sr8, msk);
            }
            if (tig == 0) {
                pst[wcol * 128 + rl]     = sr;
                pst[wcol * 128 + rl + 8] = sr8;
            }
        }
    }

    if (act == 3 && prow) {
        __syncthreads();
        if (tid < 128) {
            const float s = pst[tid] + pst[128 + tid]
                          + pst[256 + tid] + pst[384 + tid];
            prow[(long)blockIdx.x * M_ + (long)bz * L_ + bm + tid] = s;
        }
    }
}

// ---------------------------------------------------------------------------
// Merged prologue: conv_inputs (blocks 0..8191) + 4 weight transposes
// ---------------------------------------------------------------------------
__global__ __launch_bounds__(256) void prologue(
    const float* __restrict__ in, bf16* __restrict__ ib,
    const float* __restrict__ tW, bf16* __restrict__ tWt,
    const float* __restrict__ cW, bf16* __restrict__ cWt,
    const float* __restrict__ ffW, bf16* __restrict__ ffWt,
    const float* __restrict__ frW, bf16* __restrict__ frWt)
{
    const int bid = blockIdx.x;
    if (bid < 8192) {
        const int i = bid * 256 + threadIdx.x;     // over M*U/4
        const float4 v = ((const float4*)in)[i];
        *(bf162*)(ib + (long)i * 4)     = __floats2bfloat162_rn(v.x, v.y);
        *(bf162*)(ib + (long)i * 4 + 2) = __floats2bfloat162_rn(v.z, v.w);
        return;
    }
    __shared__ float tile[32][33];
    const int s = bid - 8192;
    const int job = s >> 9;
    const int r   = s & 511;
    const float* src; bf16* dst; int R, Cc, r0, c0;
    if (job < 2) {
        const int layer = r >> 8, w = r & 255;
        src = (job == 0 ? tW : cW) + (long)layer * U_ * U_;
        dst = (job == 0 ? tWt : cWt) + (long)layer * U_ * U_;
        R = U_; Cc = U_; c0 = (w & 15) * 32; r0 = (w >> 4) * 32;
    } else {
        src = (job == 2 ? ffW : frW);
        dst = (job == 2 ? ffWt : frWt);
        R = 2 * U_; Cc = U_; c0 = (r & 15) * 32; r0 = (r >> 4) * 32;
    }
    const int tx = threadIdx.x & 31, ty = threadIdx.x >> 5;
    #pragma unroll
    for (int i2 = 0; i2 < 32; i2 += 8)
        tile[ty + i2][tx] = src[(long)(r0 + ty + i2) * Cc + c0 + tx];
    __syncthreads();
    #pragma unroll
    for (int i2 = 0; i2 < 32; i2 += 8)
        dst[(long)(c0 + ty + i2) * R + r0 + tx] = __float2bfloat16(tile[tx][ty + i2]);
}

// ---------------------------------------------------------------------------
// Launch
// ---------------------------------------------------------------------------
#define GEMM_SMEM (2 * NSTG * STAGE_B)   // 96 KB  (single GEMM)
#define DUAL_SMEM (3 * NSTG * STAGE_B)   // 144 KB (dual GEMM)

extern "C" void kernel_launch(void* const* d_in, const int* in_sizes, int n_in,
                              void* d_out, int out_size)
{
    (void)in_sizes; (void)n_in; (void)out_size;
    const float* inputs = (const float*)d_in[0];
    const float* tW     = (const float*)d_in[1];
    const float* tb     = (const float*)d_in[2];
    const float* cW     = (const float*)d_in[3];
    const float* cb     = (const float*)d_in[4];
    const float* aW     = (const float*)d_in[5];
    const float* ab     = (const float*)d_in[6];
    const float* frW    = (const float*)d_in[7];
    const float* frb    = (const float*)d_in[8];
    const float* ffW    = (const float*)d_in[9];
    const float* ffb    = (const float*)d_in[10];
    float* out = (float*)d_out;

    float *ps1, *ps2, *pr;
    bf16 *ib, *x0b, *x1b, *xw3, *x1t, *att, *As, *tWt, *cWt, *ffWt, *frWt;
    cudaGetSymbolAddress((void**)&ps1,  g_ps1);
    cudaGetSymbolAddress((void**)&ps2,  g_ps2);
    cudaGetSymbolAddress((void**)&pr,   g_pr);
    cudaGetSymbolAddress((void**)&ib,   g_ib);
    cudaGetSymbolAddress((void**)&x0b,  g_x0b);
    cudaGetSymbolAddress((void**)&x1b,  g_x1b);
    cudaGetSymbolAddress((void**)&xw3,  g_xw3);
    cudaGetSymbolAddress((void**)&x1t,  g_x1t);
    cudaGetSymbolAddress((void**)&att,  g_att);
    cudaGetSymbolAddress((void**)&As,   g_As);
    cudaGetSymbolAddress((void**)&tWt,  g_tWt);
    cudaGetSymbolAddress((void**)&cWt,  g_cWt);
    cudaGetSymbolAddress((void**)&ffWt, g_ffWt);
    cudaGetSymbolAddress((void**)&frWt, g_frWt);

    cudaFuncSetAttribute(gemm_bf, cudaFuncAttributeMaxDynamicSharedMemorySize,
                         GEMM_SMEM);
    cudaFuncSetAttribute(gemm_dual, cudaFuncAttributeMaxDynamicSharedMemorySize,
                         DUAL_SMEM);

    // 1. merged prologue (inputs->bf16, 4 weight transposes)
    prologue<<<10240, 256>>>(inputs, ib, tW, tWt, cW, cWt,
                             ffW, ffWt, frW, frWt);

    dim3 gHW(U_/128, M_/128);      // (4,128)
    // 2. highway layer 0 (dual)
    gemm_dual<<<gHW, 256, DUAL_SMEM>>>(ib, nullptr, 64, tWt, cWt, U_,
                                       nullptr, x0b, inputs, nullptr, U_,
                                       tb, cb, 0, nullptr, nullptr, nullptr,
                                       nullptr, nullptr, nullptr);
    // 3. highway layer 1 (dual) + fused xw3, x1^T, s1/s2 partials
    gemm_dual<<<gHW, 256, DUAL_SMEM>>>(x0b, nullptr, 64, tWt + U_*U_, cWt + U_*U_, U_,
                                       nullptr, x1b, nullptr, x0b, U_,
                                       tb + U_, cb + U_, 0,
                                       aW + 2*U_, xw3, x1t,
                                       aW, ps1, ps2);

    // 4. scores: As[b] = exp(relu( xw3 @ x1^T + Σps1 + Σps2 + ab )) + rowsum partials
    dim3 gS(L_/128, L_/128, B_);
    gemm_bf<<<gS, 256, GEMM_SMEM>>>(xw3, U_, (long)L_*U_, x1b, U_, (long)L_*U_,
                                    As, L_, (long)L_*L_, U_,
                                    ps1, L_, 4, ps2, L_, 4, ab,
                                    nullptr, 0, 0, 3, pr);

    // 5. att = (expA @ x1) * (1/Σpr)[row] -> bf16 att [M,512]
    dim3 gAtt(U_/128, L_/128, B_);
    gemm_bf<<<gAtt, 256, GEMM_SMEM>>>(As, L_, (long)L_*L_, x1t, L_, (long)U_*L_,
                                      att, U_, (long)L_*U_, L_,
                                      nullptr, 0, 0, nullptr, 0, 0, nullptr,
                                      pr, L_, 8, 0, nullptr);

    // 6. final dual over implicit concat [ib | att]:
    //    out = sig(.@frW+frb)*inputs + sig(.@ffW+ffb)^2
    gemm_dual<<<gHW, 256, DUAL_SMEM>>>(ib, att, 8, ffWt, frWt, 2*U_,
                                       out, nullptr, inputs, nullptr, 2*U_,
                                       ffb, frb, 1, nullptr, nullptr, nullptr,
                                       nullptr, nullptr, nullptr);
}